// round 4
// baseline (speedup 1.0000x reference)
#include <cuda_runtime.h>
#include <cuda_fp16.h>

#define NB 4
#define CG 9
#define DD 16
#define DCELLS (DD*DD*DD)       // 4096 cells
#define HWSZ (1024*1024)

// Projected grid: per cell, channels {0,1,2} as fp16 packed in 8B (uint2).
// 4 * 4096 * 8B = 128KB static device scratch.
__device__ uint2 d_pgrid[NB * DCELLS];

// ---------------------------------------------------------------------------
// Kernel 1: project 9-channel grid through conv_w[:, :9] -> fp16x3 per cell.
// ---------------------------------------------------------------------------
__global__ void project_grid_kernel(const float* __restrict__ grid,
                                    const float* __restrict__ cw) {
    int idx = blockIdx.x * blockDim.x + threadIdx.x;
    if (idx >= NB * DCELLS) return;
    int n    = idx >> 12;       // / 4096
    int cell = idx & 4095;

    float a0 = 0.f, a1 = 0.f, a2 = 0.f;
    const float* g = grid + (size_t)n * CG * DCELLS + cell;
#pragma unroll
    for (int c = 0; c < CG; c++) {
        float v = g[c * DCELLS];
        a0 = fmaf(cw[0 * 12 + c], v, a0);
        a1 = fmaf(cw[1 * 12 + c], v, a1);
        a2 = fmaf(cw[2 * 12 + c], v, a2);
    }

    __half2 h01 = __floats2half2_rn(a0, a1);
    __half2 h2_ = __floats2half2_rn(a2, 0.f);
    uint2 e;
    e.x = *(const unsigned int*)&h01;
    e.y = *(const unsigned int*)&h2_;
    d_pgrid[idx] = e;
}

// ---------------------------------------------------------------------------
// Kernel 2: fused slice + conv. 32KB fp16 table in smem -> 7 CTAs/SM possible;
// launch_bounds caps regs for 6 CTAs/SM (48 warps). 8x LDS.64 gathers/pixel.
// ---------------------------------------------------------------------------
struct F3 { float x, y, z; };

__device__ __forceinline__ F3 unpack3(uint2 e) {
    float2 p0 = __half22float2(*(const __half2*)&e.x);
    float2 p1 = __half22float2(*(const __half2*)&e.y);
    F3 r; r.x = p0.x; r.y = p0.y; r.z = p1.x;
    return r;
}

__device__ __forceinline__ F3 lerp3(F3 a, F3 b, float t) {
    F3 r;
    r.x = fmaf(t, b.x - a.x, a.x);
    r.y = fmaf(t, b.y - a.y, a.y);
    r.z = fmaf(t, b.z - a.z, a.z);
    return r;
}

__global__ __launch_bounds__(256, 6) void slice_conv_kernel(
    const float* __restrict__ guide,
    const float* __restrict__ cw,
    const float* __restrict__ cb,
    float* __restrict__ out)
{
    __shared__ uint2 sg[DCELLS];   // 32 KB
    const int n = blockIdx.y;

    // Stage this image's projected table (vectorized 16B copies).
    {
        const uint4* src = (const uint4*)(d_pgrid + n * DCELLS);
        uint4* dst = (uint4*)sg;
        for (int i = threadIdx.x; i < DCELLS / 2; i += blockDim.x) dst[i] = src[i];
    }
    __syncthreads();

    const float wr9 = cw[ 9], wr10 = cw[10], wr11 = cw[11], br = cb[0];
    const float wg9 = cw[21], wg10 = cw[22], wg11 = cw[23], bg = cb[1];
    const float wb9 = cw[33], wb10 = cw[34], wb11 = cw[35], bb = cb[2];

    const float4* gR = (const float4*)(guide + (size_t)(n * 3 + 0) * HWSZ);
    const float4* gG = (const float4*)(guide + (size_t)(n * 3 + 1) * HWSZ);
    const float4* gB = (const float4*)(guide + (size_t)(n * 3 + 2) * HWSZ);
    float4* oR = (float4*)(out + (size_t)(n * 3 + 0) * HWSZ);
    float4* oG = (float4*)(out + (size_t)(n * 3 + 1) * HWSZ);
    float4* oB = (float4*)(out + (size_t)(n * 3 + 2) * HWSZ);

    const int nq     = HWSZ / 4;
    const int stride = gridDim.x * blockDim.x;

    for (int q = blockIdx.x * blockDim.x + threadIdx.x; q < nq; q += stride) {
        float4 r4 = gR[q];
        float4 g4 = gG[q];
        float4 b4 = gB[q];
        float4 or4, og4, ob4;

        const float* rr = (const float*)&r4;
        const float* gg = (const float*)&g4;
        const float* bv = (const float*)&b4;
        float* po0 = (float*)&or4;
        float* po1 = (float*)&og4;
        float* po2 = (float*)&ob4;

#pragma unroll
        for (int e = 0; e < 4; e++) {
            float r = rr[e], g = gg[e], b = bv[e];

            float crd = fminf(fmaxf(r, 0.f), 1.f) * 15.f;
            float cgd = fminf(fmaxf(g, 0.f), 1.f) * 15.f;
            float cbd = fminf(fmaxf(b, 0.f), 1.f) * 15.f;
            int ir = (int)crd; ir = ir > 14 ? 14 : ir;
            int ig = (int)cgd; ig = ig > 14 ? 14 : ig;
            int ib = (int)cbd; ib = ib > 14 ? 14 : ib;
            float fr = crd - (float)ir;
            float fg = cgd - (float)ig;
            float fb = cbd - (float)ib;

            int base = ir * 256 + ig * 16 + ib;

            uint2 e000 = sg[base      ], e001 = sg[base +   1];
            uint2 e010 = sg[base +  16], e011 = sg[base +  17];
            uint2 e100 = sg[base + 256], e101 = sg[base + 257];
            uint2 e110 = sg[base + 272], e111 = sg[base + 273];

            F3 c00 = lerp3(unpack3(e000), unpack3(e001), fb);
            F3 c01 = lerp3(unpack3(e010), unpack3(e011), fb);
            F3 c10 = lerp3(unpack3(e100), unpack3(e101), fb);
            F3 c11 = lerp3(unpack3(e110), unpack3(e111), fb);
            F3 c0  = lerp3(c00, c01, fg);
            F3 c1  = lerp3(c10, c11, fg);
            F3 cc  = lerp3(c0, c1, fr);

            po0[e] = fmaf(wr11, b, fmaf(wr10, g, fmaf(wr9, r, cc.x + br)));
            po1[e] = fmaf(wg11, b, fmaf(wg10, g, fmaf(wg9, r, cc.y + bg)));
            po2[e] = fmaf(wb11, b, fmaf(wb10, g, fmaf(wb9, r, cc.z + bb)));
        }

        oR[q] = or4;
        oG[q] = og4;
        oB[q] = ob4;
    }
}

// ---------------------------------------------------------------------------
// Launch
// ---------------------------------------------------------------------------
extern "C" void kernel_launch(void* const* d_in, const int* in_sizes, int n_in,
                              void* d_out, int out_size) {
    const float* grid  = (const float*)d_in[0];   // (4,9,16,16,16)
    const float* guide = (const float*)d_in[1];   // (4,3,1024,1024)
    const float* cw    = (const float*)d_in[2];   // (3,12)
    const float* cb    = (const float*)d_in[3];   // (3,)
    float* out = (float*)d_out;                   // (4,3,1024,1024)

    project_grid_kernel<<<(NB * DCELLS + 255) / 256, 256>>>(grid, cw);

    dim3 blocks(222, NB);   // 888 CTAs = 148 SMs x 6 CTAs/SM (32KB smem each)
    slice_conv_kernel<<<blocks, 256>>>(guide, cw, cb, out);
}

// round 5
// speedup vs baseline: 1.0962x; 1.0962x over previous
#include <cuda_runtime.h>
#include <cuda_fp16.h>

#define NB 4
#define CG 9
#define DD 16
#define DCELLS (DD*DD*DD)       // 4096 cells
#define HWSZ (1024*1024)

// Packed projected grid: per entry (r,g,b): 6 halves = channels {0,1,2} of cell b
// followed by channels {0,1,2} of cell b+1, padded to 16B. 4 * 4096 * 16B = 256KB.
__device__ uint4 d_pgrid[NB * DCELLS];

// ---------------------------------------------------------------------------
// Kernel 1: project 9-channel grid through conv_w[:, :9] -> packed fp16 pairs.
// ---------------------------------------------------------------------------
__global__ void project_grid_kernel(const float* __restrict__ grid,
                                    const float* __restrict__ cw) {
    int idx = blockIdx.x * blockDim.x + threadIdx.x;
    if (idx >= NB * DCELLS) return;
    int n    = idx >> 12;       // / 4096
    int cell = idx & 4095;      // r*256 + g*16 + b
    int b    = cell & 15;

    const float* g0 = grid + (size_t)n * CG * DCELLS + cell;
    int hoff = (b < 15) ? 1 : 0;

    float lo0 = 0.f, lo1 = 0.f, lo2 = 0.f;
    float hi0 = 0.f, hi1 = 0.f, hi2 = 0.f;
#pragma unroll
    for (int c = 0; c < CG; c++) {
        float vl = g0[c * DCELLS];
        float vh = g0[c * DCELLS + hoff];
        float w0 = cw[0 * 12 + c], w1 = cw[1 * 12 + c], w2 = cw[2 * 12 + c];
        lo0 = fmaf(w0, vl, lo0); lo1 = fmaf(w1, vl, lo1); lo2 = fmaf(w2, vl, lo2);
        hi0 = fmaf(w0, vh, hi0); hi1 = fmaf(w1, vh, hi1); hi2 = fmaf(w2, vh, hi2);
    }

    __half2 h01 = __floats2half2_rn(lo0, lo1);   // (c0(b),  c1(b))
    __half2 h23 = __floats2half2_rn(lo2, hi0);   // (c2(b),  c0(b+1))
    __half2 h45 = __floats2half2_rn(hi1, hi2);   // (c1(b+1),c2(b+1))

    uint4 e;
    e.x = *(const unsigned int*)&h01;
    e.y = *(const unsigned int*)&h23;
    e.z = *(const unsigned int*)&h45;
    e.w = 0u;
    d_pgrid[idx] = e;
}

// ---------------------------------------------------------------------------
// Kernel 2: fused slice + conv. 64KB b-pair table in smem; 4x LDS.128/pixel.
// 384 threads, 3 CTAs/SM -> 36 warps/SM.
// ---------------------------------------------------------------------------
struct F3 { float x, y, z; };

__device__ __forceinline__ F3 unpack_lerp_b(uint4 e, float fb) {
    float2 p0 = __half22float2(*(const __half2*)&e.x);   // c0(b), c1(b)
    float2 p1 = __half22float2(*(const __half2*)&e.y);   // c2(b), c0(b+1)
    float2 p2 = __half22float2(*(const __half2*)&e.z);   // c1(b+1), c2(b+1)
    F3 r;
    r.x = fmaf(fb, p1.y - p0.x, p0.x);
    r.y = fmaf(fb, p2.x - p0.y, p0.y);
    r.z = fmaf(fb, p2.y - p1.x, p1.x);
    return r;
}

__device__ __forceinline__ F3 lerp3(F3 a, F3 b, float t) {
    F3 r;
    r.x = fmaf(t, b.x - a.x, a.x);
    r.y = fmaf(t, b.y - a.y, a.y);
    r.z = fmaf(t, b.z - a.z, a.z);
    return r;
}

__global__ __launch_bounds__(384, 3) void slice_conv_kernel(
    const float* __restrict__ guide,
    const float* __restrict__ cw,
    const float* __restrict__ cb,
    float* __restrict__ out)
{
    extern __shared__ uint4 sg[];   // 4096 * 16B = 64 KB
    const int n = blockIdx.y;

    const uint4* pg = d_pgrid + n * DCELLS;
    for (int i = threadIdx.x; i < DCELLS; i += blockDim.x) sg[i] = pg[i];
    __syncthreads();

    const float wr9 = cw[ 9], wr10 = cw[10], wr11 = cw[11], br = cb[0];
    const float wg9 = cw[21], wg10 = cw[22], wg11 = cw[23], bg = cb[1];
    const float wb9 = cw[33], wb10 = cw[34], wb11 = cw[35], bb = cb[2];

    const float4* gR = (const float4*)(guide + (size_t)(n * 3 + 0) * HWSZ);
    const float4* gG = (const float4*)(guide + (size_t)(n * 3 + 1) * HWSZ);
    const float4* gB = (const float4*)(guide + (size_t)(n * 3 + 2) * HWSZ);
    float4* oR = (float4*)(out + (size_t)(n * 3 + 0) * HWSZ);
    float4* oG = (float4*)(out + (size_t)(n * 3 + 1) * HWSZ);
    float4* oB = (float4*)(out + (size_t)(n * 3 + 2) * HWSZ);

    const int nq     = HWSZ / 4;
    const int stride = gridDim.x * blockDim.x;

    for (int q = blockIdx.x * blockDim.x + threadIdx.x; q < nq; q += stride) {
        float4 r4 = gR[q];
        float4 g4 = gG[q];
        float4 b4 = gB[q];
        float4 or4, og4, ob4;

        const float* rr = (const float*)&r4;
        const float* gg = (const float*)&g4;
        const float* bv = (const float*)&b4;
        float* po0 = (float*)&or4;
        float* po1 = (float*)&og4;
        float* po2 = (float*)&ob4;

#pragma unroll
        for (int e = 0; e < 4; e++) {
            float r = rr[e], g = gg[e], b = bv[e];

            float crd = fminf(fmaxf(r, 0.f), 1.f) * 15.f;
            float cgd = fminf(fmaxf(g, 0.f), 1.f) * 15.f;
            float cbd = fminf(fmaxf(b, 0.f), 1.f) * 15.f;
            int ir = (int)crd; ir = ir > 14 ? 14 : ir;
            int ig = (int)cgd; ig = ig > 14 ? 14 : ig;
            int ib = (int)cbd; ib = ib > 14 ? 14 : ib;
            float fr = crd - (float)ir;
            float fg = cgd - (float)ig;
            float fb = cbd - (float)ib;

            int base = ir * 256 + ig * 16 + ib;

            // 4 gathers; each entry contains both b-endpoints of its corner.
            uint4 e00 = sg[base];
            uint4 e01 = sg[base +  16];
            uint4 e10 = sg[base + 256];
            uint4 e11 = sg[base + 272];

            F3 c00 = unpack_lerp_b(e00, fb);
            F3 c01 = unpack_lerp_b(e01, fb);
            F3 c10 = unpack_lerp_b(e10, fb);
            F3 c11 = unpack_lerp_b(e11, fb);
            F3 c0  = lerp3(c00, c01, fg);
            F3 c1  = lerp3(c10, c11, fg);
            F3 cc  = lerp3(c0, c1, fr);

            po0[e] = fmaf(wr11, b, fmaf(wr10, g, fmaf(wr9, r, cc.x + br)));
            po1[e] = fmaf(wg11, b, fmaf(wg10, g, fmaf(wg9, r, cc.y + bg)));
            po2[e] = fmaf(wb11, b, fmaf(wb10, g, fmaf(wb9, r, cc.z + bb)));
        }

        oR[q] = or4;
        oG[q] = og4;
        oB[q] = ob4;
    }
}

// ---------------------------------------------------------------------------
// Launch
// ---------------------------------------------------------------------------
extern "C" void kernel_launch(void* const* d_in, const int* in_sizes, int n_in,
                              void* d_out, int out_size) {
    const float* grid  = (const float*)d_in[0];   // (4,9,16,16,16)
    const float* guide = (const float*)d_in[1];   // (4,3,1024,1024)
    const float* cw    = (const float*)d_in[2];   // (3,12)
    const float* cb    = (const float*)d_in[3];   // (3,)
    float* out = (float*)d_out;                   // (4,3,1024,1024)

    cudaFuncSetAttribute(slice_conv_kernel,
                         cudaFuncAttributeMaxDynamicSharedMemorySize, 65536);

    project_grid_kernel<<<(NB * DCELLS + 255) / 256, 256>>>(grid, cw);

    dim3 blocks(111, NB);   // 444 CTAs = 148 SMs x 3 CTAs/SM (64KB smem each)
    slice_conv_kernel<<<blocks, 384, 65536>>>(guide, cw, cb, out);
}

// round 6
// speedup vs baseline: 1.1721x; 1.0692x over previous
#include <cuda_runtime.h>
#include <cuda_fp16.h>

#define NB 4
#define CG 9
#define DD 16
#define DCELLS (DD*DD*DD)       // 4096 cells
#define HWSZ (1024*1024)

// Packed projected grid: per entry (r,g,b): 6 halves = channels {0,1,2} of cell b
// followed by channels {0,1,2} of cell b+1, padded to 16B. 4 * 4096 * 16B = 256KB.
__device__ uint4 d_pgrid[NB * DCELLS];

// ---------------------------------------------------------------------------
// Kernel 1: project 9-channel grid through conv_w[:, :9] -> packed fp16 pairs.
// Each thread computes ONLY its own cell (9 coalesced loads); the b+1
// neighbor's projected values come from lane+1 via shfl. Lanes with b==15
// (lanes 15 and 31 of each warp) receive garbage from shfl, but their
// hi-halves are never read by the slice kernel (ib <= 14).
// ---------------------------------------------------------------------------
__global__ void project_grid_kernel(const float* __restrict__ grid,
                                    const float* __restrict__ cw) {
    int idx = blockIdx.x * blockDim.x + threadIdx.x;
    if (idx >= NB * DCELLS) return;
    int n    = idx >> 12;       // / 4096
    int cell = idx & 4095;      // r*256 + g*16 + b

    const float* g0 = grid + (size_t)n * CG * DCELLS + cell;

    float a0 = 0.f, a1 = 0.f, a2 = 0.f;
#pragma unroll
    for (int c = 0; c < CG; c++) {
        float v = g0[c * DCELLS];
        a0 = fmaf(cw[0 * 12 + c], v, a0);
        a1 = fmaf(cw[1 * 12 + c], v, a1);
        a2 = fmaf(cw[2 * 12 + c], v, a2);
    }

    // Neighbor (cell+1, i.e. b+1) projected values from lane+1.
    float h0 = __shfl_down_sync(0xFFFFFFFFu, a0, 1);
    float h1 = __shfl_down_sync(0xFFFFFFFFu, a1, 1);
    float h2 = __shfl_down_sync(0xFFFFFFFFu, a2, 1);

    __half2 h01 = __floats2half2_rn(a0, a1);   // (c0(b),  c1(b))
    __half2 h23 = __floats2half2_rn(a2, h0);   // (c2(b),  c0(b+1))
    __half2 h45 = __floats2half2_rn(h1, h2);   // (c1(b+1),c2(b+1))

    uint4 e;
    e.x = *(const unsigned int*)&h01;
    e.y = *(const unsigned int*)&h23;
    e.z = *(const unsigned int*)&h45;
    e.w = 0u;
    d_pgrid[idx] = e;
}

// ---------------------------------------------------------------------------
// Kernel 2: fused slice + conv. 64KB b-pair table in smem; 4x LDS.128/pixel.
// 256 threads, 3 CTAs/SM. Guide loads software-pipelined, streaming hints.
// ---------------------------------------------------------------------------
struct F3 { float x, y, z; };

__device__ __forceinline__ F3 unpack_lerp_b(uint4 e, float fb) {
    float2 p0 = __half22float2(*(const __half2*)&e.x);   // c0(b), c1(b)
    float2 p1 = __half22float2(*(const __half2*)&e.y);   // c2(b), c0(b+1)
    float2 p2 = __half22float2(*(const __half2*)&e.z);   // c1(b+1), c2(b+1)
    F3 r;
    r.x = fmaf(fb, p1.y - p0.x, p0.x);
    r.y = fmaf(fb, p2.x - p0.y, p0.y);
    r.z = fmaf(fb, p2.y - p1.x, p1.x);
    return r;
}

__device__ __forceinline__ F3 lerp3(F3 a, F3 b, float t) {
    F3 r;
    r.x = fmaf(t, b.x - a.x, a.x);
    r.y = fmaf(t, b.y - a.y, a.y);
    r.z = fmaf(t, b.z - a.z, a.z);
    return r;
}

__global__ __launch_bounds__(256) void slice_conv_kernel(
    const float* __restrict__ guide,
    const float* __restrict__ cw,
    const float* __restrict__ cb,
    float* __restrict__ out)
{
    extern __shared__ uint4 sg[];   // 4096 * 16B = 64 KB
    const int n = blockIdx.y;

    const uint4* pg = d_pgrid + n * DCELLS;
    for (int i = threadIdx.x; i < DCELLS; i += blockDim.x) sg[i] = pg[i];
    __syncthreads();

    const float wr9 = cw[ 9], wr10 = cw[10], wr11 = cw[11], br = cb[0];
    const float wg9 = cw[21], wg10 = cw[22], wg11 = cw[23], bg = cb[1];
    const float wb9 = cw[33], wb10 = cw[34], wb11 = cw[35], bb = cb[2];

    const float4* gR = (const float4*)(guide + (size_t)(n * 3 + 0) * HWSZ);
    const float4* gG = (const float4*)(guide + (size_t)(n * 3 + 1) * HWSZ);
    const float4* gB = (const float4*)(guide + (size_t)(n * 3 + 2) * HWSZ);
    float4* oR = (float4*)(out + (size_t)(n * 3 + 0) * HWSZ);
    float4* oG = (float4*)(out + (size_t)(n * 3 + 1) * HWSZ);
    float4* oB = (float4*)(out + (size_t)(n * 3 + 2) * HWSZ);

    const int nq     = HWSZ / 4;
    const int stride = gridDim.x * blockDim.x;

    int q = blockIdx.x * blockDim.x + threadIdx.x;
    if (q >= nq) return;

    // Prime the pipeline.
    float4 r4 = __ldcs(gR + q);
    float4 g4 = __ldcs(gG + q);
    float4 b4 = __ldcs(gB + q);

    while (q < nq) {
        // Prefetch next iteration's guide while we chew on this one.
        int qn = q + stride;
        float4 rn, gn, bn;
        if (qn < nq) {
            rn = __ldcs(gR + qn);
            gn = __ldcs(gG + qn);
            bn = __ldcs(gB + qn);
        }

        float4 or4, og4, ob4;
        const float* rr = (const float*)&r4;
        const float* gg = (const float*)&g4;
        const float* bv = (const float*)&b4;
        float* po0 = (float*)&or4;
        float* po1 = (float*)&og4;
        float* po2 = (float*)&ob4;

#pragma unroll
        for (int e = 0; e < 4; e++) {
            float r = rr[e], g = gg[e], b = bv[e];

            float crd = fminf(fmaxf(r, 0.f), 1.f) * 15.f;
            float cgd = fminf(fmaxf(g, 0.f), 1.f) * 15.f;
            float cbd = fminf(fmaxf(b, 0.f), 1.f) * 15.f;
            int ir = (int)crd; ir = ir > 14 ? 14 : ir;
            int ig = (int)cgd; ig = ig > 14 ? 14 : ig;
            int ib = (int)cbd; ib = ib > 14 ? 14 : ib;
            float fr = crd - (float)ir;
            float fg = cgd - (float)ig;
            float fb = cbd - (float)ib;

            int base = ir * 256 + ig * 16 + ib;

            uint4 e00 = sg[base];
            uint4 e01 = sg[base +  16];
            uint4 e10 = sg[base + 256];
            uint4 e11 = sg[base + 272];

            F3 c00 = unpack_lerp_b(e00, fb);
            F3 c01 = unpack_lerp_b(e01, fb);
            F3 c10 = unpack_lerp_b(e10, fb);
            F3 c11 = unpack_lerp_b(e11, fb);
            F3 c0  = lerp3(c00, c01, fg);
            F3 c1  = lerp3(c10, c11, fg);
            F3 cc  = lerp3(c0, c1, fr);

            po0[e] = fmaf(wr11, b, fmaf(wr10, g, fmaf(wr9, r, cc.x + br)));
            po1[e] = fmaf(wg11, b, fmaf(wg10, g, fmaf(wg9, r, cc.y + bg)));
            po2[e] = fmaf(wb11, b, fmaf(wb10, g, fmaf(wb9, r, cc.z + bb)));
        }

        __stcs(oR + q, or4);
        __stcs(oG + q, og4);
        __stcs(oB + q, ob4);

        q = qn;
        r4 = rn; g4 = gn; b4 = bn;
    }
}

// ---------------------------------------------------------------------------
// Launch
// ---------------------------------------------------------------------------
extern "C" void kernel_launch(void* const* d_in, const int* in_sizes, int n_in,
                              void* d_out, int out_size) {
    const float* grid  = (const float*)d_in[0];   // (4,9,16,16,16)
    const float* guide = (const float*)d_in[1];   // (4,3,1024,1024)
    const float* cw    = (const float*)d_in[2];   // (3,12)
    const float* cb    = (const float*)d_in[3];   // (3,)
    float* out = (float*)d_out;                   // (4,3,1024,1024)

    cudaFuncSetAttribute(slice_conv_kernel,
                         cudaFuncAttributeMaxDynamicSharedMemorySize, 65536);

    project_grid_kernel<<<(NB * DCELLS + 255) / 256, 256>>>(grid, cw);

    dim3 blocks(111, NB);   // 444 CTAs = 148 SMs x 3 CTAs/SM (64KB smem each)
    slice_conv_kernel<<<blocks, 256, 65536>>>(guide, cw, cb, out);
}